// round 17
// baseline (speedup 1.0000x reference)
#include <cuda_runtime.h>
#include <cuda_bf16.h>
#include <math.h>
#include <stdint.h>

#define B_ 4
#define T_ 2048
#define C_ 512
#define H_ 8
#define HD_ 64
#define TOPK_ 32
#define BH_ (B_*H_)          // 32
#define ROWS_ (BH_*T_)       // 65536
#define SPIKES_SZ ((size_t)B_*T_*C_)   // 4194304

// ------------------- cp.async helpers -------------------
__device__ __forceinline__ void cp_async16(void* smem_dst, const void* gsrc) {
    unsigned dst = (unsigned)__cvta_generic_to_shared(smem_dst);
    asm volatile("cp.async.cg.shared.global [%0], [%1], 16;" :: "r"(dst), "l"(gsrc));
}
__device__ __forceinline__ void cp_commit() {
    asm volatile("cp.async.commit_group;");
}
template<int N>
__device__ __forceinline__ void cp_wait() {
    asm volatile("cp.async.wait_group %0;" :: "n"(N));
}

// ------------------- scratch (device globals; no allocation) -------------------
__device__ float g_q[BH_*T_*HD_];        // [bh][t][d]
__device__ float g_k[BH_*T_*HD_];
__device__ float g_v[BH_*T_*HD_];
__device__ __nv_bfloat16 g_qh[BH_*T_*HD_];
__device__ __nv_bfloat16 g_kh[BH_*T_*HD_];
__device__ float g_scores[(size_t)ROWS_*T_];   // approx scores [row][tk]
__device__ float g_ctx[B_*T_*C_];        // [b][t][c]
__device__ float g_analog[B_*T_*C_];

// ------------------- GEMM: M=8192, N=512, K=512, cp.async double-buffered -------------------
// MODE 0 additionally stores bf16 copies of q,k for the tensor-core scores pass.
#define A_STRIDE 36
template<int MODE>
__global__ void __launch_bounds__(256) k_gemm(const float* __restrict__ X,
    const float* __restrict__ Wq, const float* __restrict__ Wk, const float* __restrict__ Wv,
    const float* __restrict__ bq, const float* __restrict__ bk, const float* __restrict__ bv)
{
    extern __shared__ float smg[];
    float (*As)[128][A_STRIDE] = (float(*)[128][A_STRIDE])smg;                 // 2 x 128 x 36
    float (*Bs)[32][128]       = (float(*)[32][128])(smg + 2*128*A_STRIDE);    // 2 x 32 x 128

    const float* Xp   = (MODE == 0) ? X : g_ctx;
    const float* W    = (MODE == 0) ? (blockIdx.z == 0 ? Wq : (blockIdx.z == 1 ? Wk : Wv)) : Wq;
    const float* bias = (MODE == 0) ? (blockIdx.z == 0 ? bq : (blockIdx.z == 1 ? bk : bv)) : bq;
    float* O = 0;
    __nv_bfloat16* OB = 0;
    if (MODE == 0) {
        O  = (blockIdx.z == 0 ? g_q : (blockIdx.z == 1 ? g_k : g_v));
        OB = (blockIdx.z == 0 ? g_qh : (blockIdx.z == 1 ? g_kh : 0));
    } else O = g_analog;

    const int tid = threadIdx.x;
    const int tx = tid & 15, ty = tid >> 4;
    const int m0 = blockIdx.y * 128, n0 = blockIdx.x * 128;

    float acc[8][8];
    #pragma unroll
    for (int j = 0; j < 8; j++)
        #pragma unroll
        for (int i = 0; i < 8; i++) acc[j][i] = 0.0f;

    auto prefetch = [&](int k0, int buf) {
        #pragma unroll
        for (int it = 0; it < 4; it++) {
            int f4 = tid + 256 * it;
            int r = f4 >> 3, c = f4 & 7;
            cp_async16(&As[buf][r][c*4], &Xp[(size_t)(m0 + r) * 512 + k0 + c * 4]);
        }
        #pragma unroll
        for (int it = 0; it < 4; it++) {
            int f4 = tid + 256 * it;
            int r = f4 >> 5, c4 = f4 & 31;
            cp_async16(&Bs[buf][r][c4*4], &W[(size_t)(k0 + r) * 512 + n0 + c4 * 4]);
        }
        cp_commit();
    };

    prefetch(0, 0);

    for (int t = 0; t < 16; t++) {
        const int buf = t & 1;
        if (t < 15) {
            prefetch((t + 1) * 32, buf ^ 1);
            cp_wait<1>();
        } else {
            cp_wait<0>();
        }
        __syncthreads();

        #pragma unroll 8
        for (int kk = 0; kk < 32; kk++) {
            float a[8], b[8];
            #pragma unroll
            for (int j = 0; j < 8; j++) a[j] = As[buf][ty + 16*j][kk];
            #pragma unroll
            for (int i = 0; i < 8; i++) b[i] = Bs[buf][kk][tx + 16*i];
            #pragma unroll
            for (int j = 0; j < 8; j++)
                #pragma unroll
                for (int i = 0; i < 8; i++)
                    acc[j][i] += a[j] * b[i];
        }
        __syncthreads();
    }

    #pragma unroll
    for (int j = 0; j < 8; j++) {
        int m = m0 + ty + 16*j;
        #pragma unroll
        for (int i = 0; i < 8; i++) {
            int n = n0 + tx + 16*i;
            float val = acc[j][i] + bias[n];
            if (MODE == 0) {
                int b = m >> 11, t = m & 2047;
                int h = n >> 6, d = n & 63;
                size_t idx = (((size_t)(b * H_ + h)) * T_ + t) * HD_ + d;
                O[idx] = val;
                if (blockIdx.z < 2) OB[idx] = __float2bfloat16(val);
            } else {
                O[(size_t)m * 512 + n] = val;
            }
        }
    }
}

// ------------------- approx scores via mma.sync bf16 (tensor pipe, sm_80 ISA) -------------------
// Block 256 = 8 warps; block tile 128x128; warp tile 32x64 (2 m-frags x 8 n-frags), K=64 (4 k16 steps).
// Fragments loaded as direct b32 from smem rows padded to 144B (bank (row*36+tig)%32 -> conflict-free).
#define BF_STRIDE 72   // bf16 elems per padded row (144B)
__global__ void __launch_bounds__(256) k_scores_mma(float* __restrict__ attn_out)
{
    __shared__ __align__(16) __nv_bfloat16 Qs[128 * BF_STRIDE];
    __shared__ __align__(16) __nv_bfloat16 Ks[128 * BF_STRIDE];

    const int tid = threadIdx.x;
    const int bh = blockIdx.z, m0 = blockIdx.y * 128, n0 = blockIdx.x * 128;
    const int warp = tid >> 5, lane = tid & 31;
    const int grp = lane >> 2, tig = lane & 3;
    const int wm = warp >> 1, wn = warp & 1;

    const __nv_bfloat16* Qg = g_qh + ((size_t)bh * T_ + m0) * HD_;
    const __nv_bfloat16* Kg = g_kh + ((size_t)bh * T_ + n0) * HD_;

    // load both tiles: 128 rows x 64 bf16 = 8 x 16B chunks per row
    #pragma unroll
    for (int it = 0; it < 4; it++) {
        int f = tid + 256 * it;                // 0..1023
        int r = f >> 3, c = f & 7;
        *(uint4*)&Qs[r * BF_STRIDE + c * 8] = *(const uint4*)&Qg[(size_t)r * HD_ + c * 8];
        *(uint4*)&Ks[r * BF_STRIDE + c * 8] = *(const uint4*)&Kg[(size_t)r * HD_ + c * 8];
    }
    __syncthreads();

    float acc[2][8][4];
    #pragma unroll
    for (int mf = 0; mf < 2; mf++)
        #pragma unroll
        for (int nf = 0; nf < 8; nf++)
            #pragma unroll
            for (int q = 0; q < 4; q++) acc[mf][nf][q] = 0.0f;

    #pragma unroll
    for (int ks = 0; ks < 4; ks++) {
        const int kb = ks * 16;
        uint32_t a[2][4];
        #pragma unroll
        for (int mf = 0; mf < 2; mf++) {
            int r = wm * 32 + mf * 16 + grp;
            a[mf][0] = *(const uint32_t*)&Qs[r * BF_STRIDE + kb + tig * 2];
            a[mf][1] = *(const uint32_t*)&Qs[(r + 8) * BF_STRIDE + kb + tig * 2];
            a[mf][2] = *(const uint32_t*)&Qs[r * BF_STRIDE + kb + 8 + tig * 2];
            a[mf][3] = *(const uint32_t*)&Qs[(r + 8) * BF_STRIDE + kb + 8 + tig * 2];
        }
        uint32_t b[8][2];
        #pragma unroll
        for (int nf = 0; nf < 8; nf++) {
            int n = wn * 64 + nf * 8 + grp;
            b[nf][0] = *(const uint32_t*)&Ks[n * BF_STRIDE + kb + tig * 2];
            b[nf][1] = *(const uint32_t*)&Ks[n * BF_STRIDE + kb + 8 + tig * 2];
        }
        #pragma unroll
        for (int mf = 0; mf < 2; mf++)
            #pragma unroll
            for (int nf = 0; nf < 8; nf++)
                asm volatile(
                    "mma.sync.aligned.m16n8k16.row.col.f32.bf16.bf16.f32 "
                    "{%0,%1,%2,%3}, {%4,%5,%6,%7}, {%8,%9}, {%0,%1,%2,%3};"
                    : "+f"(acc[mf][nf][0]), "+f"(acc[mf][nf][1]),
                      "+f"(acc[mf][nf][2]), "+f"(acc[mf][nf][3])
                    : "r"(a[mf][0]), "r"(a[mf][1]), "r"(a[mf][2]), "r"(a[mf][3]),
                      "r"(b[nf][0]), "r"(b[nf][1]));
    }

    // store approx scores (x0.125)
    float* Sb = g_scores + (size_t)bh * T_ * T_;
    #pragma unroll
    for (int mf = 0; mf < 2; mf++) {
        int m = m0 + wm * 32 + mf * 16 + grp;
        #pragma unroll
        for (int nf = 0; nf < 8; nf++) {
            int n = n0 + wn * 64 + nf * 8 + tig * 2;
            float2 v0 = make_float2(acc[mf][nf][0] * 0.125f, acc[mf][nf][1] * 0.125f);
            float2 v1 = make_float2(acc[mf][nf][2] * 0.125f, acc[mf][nf][3] * 0.125f);
            *(float2*)&Sb[(size_t)m * T_ + n]       = v0;
            *(float2*)&Sb[(size_t)(m + 8) * T_ + n] = v1;
        }
    }

    // zero-fill this block's tile of the attn output
    {
        const float4 z = make_float4(0.f, 0.f, 0.f, 0.f);
        int r = tid >> 1, part = tid & 1;
        float4* dst = (float4*)(attn_out + ((size_t)(bh * T_ + m0 + r)) * T_ + n0) + part * 16;
        #pragma unroll
        for (int i = 0; i < 16; i++) dst[i] = z;
    }
}

// ------------------- sorted-32 insert (warp-collective) -------------------
__device__ __forceinline__ void ins32(float& v, int& ix, float xv, int xi) {
    const unsigned FULL = 0xffffffffu;
    int lane = threadIdx.x & 31;
    unsigned ge = __ballot_sync(FULL, v >= xv);
    int pos = __popc(ge);
    float pv = __shfl_up_sync(FULL, v, 1);
    int   pi = __shfl_up_sync(FULL, ix, 1);
    if (lane >= pos) {            // pos==32 -> no-op (self-guarding)
        v  = (lane == pos) ? xv : pv;
        ix = (lane == pos) ? xi : pi;
    }
}

// ------------------- approx top-64 + exact rescore + exact top-32 + softmax + scatter + context -------------------
__global__ void __launch_bounds__(256) k_topkctx(float* __restrict__ attn_out)
{
    const unsigned FULL = 0xffffffffu;
    int warp = threadIdx.x >> 5, lane = threadIdx.x & 31;
    int row = blockIdx.x * 8 + warp;
    const float4* r4 = (const float4*)(g_scores + (size_t)row * T_);

    float lv = -INFINITY; int li = 0;   // primary sorted top-32 (approx)
    float sv = -INFINITY; int si = 0;   // secondary sorted 33..64 (approx)

    for (int cb = 0; cb < 16; cb += 8) {
        float4 e8[8];
        #pragma unroll
        for (int j = 0; j < 8; j++) e8[j] = __ldcs(&r4[(cb + j) * 32 + lane]);

        #pragma unroll
        for (int j = 0; j < 8; j++) {
            float v4[4] = {e8[j].x, e8[j].y, e8[j].z, e8[j].w};
            int base = ((cb + j) * 32 + lane) * 4;
            #pragma unroll
            for (int k = 0; k < 4; k++) {
                float e = v4[k];
                int idx = base + k;
                float thrP = __shfl_sync(FULL, lv, 31);
                unsigned maskP = __ballot_sync(FULL, e > thrP);
                unsigned maskAll = maskP;
                while (maskP) {
                    int src = __ffs(maskP) - 1;
                    maskP &= maskP - 1;
                    float xv = __shfl_sync(FULL, e, src);
                    int   xi = __shfl_sync(FULL, idx, src);
                    unsigned ge = __ballot_sync(FULL, lv >= xv);
                    int pos = __popc(ge);
                    if (pos < 32) {
                        float ev  = __shfl_sync(FULL, lv, 31);   // evictee (pre-insert slot 31)
                        int   evi = __shfl_sync(FULL, li, 31);
                        float pv = __shfl_up_sync(FULL, lv, 1);
                        int   pi = __shfl_up_sync(FULL, li, 1);
                        if (lane >= pos) {
                            lv = (lane == pos) ? xv : pv;
                            li = (lane == pos) ? xi : pi;
                        }
                        ins32(sv, si, ev, evi);                  // evictee -> secondary
                    } else {
                        ins32(sv, si, xv, xi);                   // rejected -> secondary
                    }
                }
                float thrS = __shfl_sync(FULL, sv, 31);
                unsigned maskS = __ballot_sync(FULL, e > thrS) & ~maskAll;
                while (maskS) {
                    int src = __ffs(maskS) - 1;
                    maskS &= maskS - 1;
                    float xv = __shfl_sync(FULL, e, src);
                    int   xi = __shfl_sync(FULL, idx, src);
                    ins32(sv, si, xv, xi);
                }
            }
        }
    }

    // exact rescore of the 64 candidates — identical fp32 FMA chain (d ascending) to the old exact GEMM
    int bh = row >> 11, t = row & 2047;
    const float* qrow = g_q + ((size_t)bh * T_ + t) * HD_;
    const float* Kb   = g_k + (size_t)bh * T_ * HD_;
    float qa = qrow[lane], qb = qrow[lane + 32];
    const float* krP = Kb + (size_t)li * HD_;
    const float* krS = Kb + (size_t)si * HD_;
    float accP = 0.f, accS = 0.f;
    #pragma unroll
    for (int d = 0; d < 64; d++) {
        float qd = __shfl_sync(FULL, (d < 32) ? qa : qb, d & 31);
        accP = fmaf(qd, krP[d], accP);
        accS = fmaf(qd, krS[d], accS);
    }
    accP *= 0.125f;
    accS *= 0.125f;
    if (!(sv > -INFINITY)) accS = -INFINITY;   // unfilled secondary slots never selected

    // exact top-32 of the 64 candidates
    float fv = -INFINITY; int fi = 0;
    {
        float thr = __shfl_sync(FULL, fv, 31);
        unsigned m = __ballot_sync(FULL, accP > thr);
        while (m) {
            int src = __ffs(m) - 1; m &= m - 1;
            float xv = __shfl_sync(FULL, accP, src);
            int   xi = __shfl_sync(FULL, li, src);
            ins32(fv, fi, xv, xi);
        }
        thr = __shfl_sync(FULL, fv, 31);
        m = __ballot_sync(FULL, accS > thr);
        while (m) {
            int src = __ffs(m) - 1; m &= m - 1;
            float xv = __shfl_sync(FULL, accS, src);
            int   xi = __shfl_sync(FULL, si, src);
            ins32(fv, fi, xv, xi);
        }
    }

    // softmax over exact top-32 (lane 0 = max), scatter, context — identical to prior rounds
    float mx = __shfl_sync(FULL, fv, 0);
    float p = expf(fv - mx);
    float s = p;
    #pragma unroll
    for (int o = 16; o; o >>= 1) s += __shfl_xor_sync(FULL, s, o);
    p /= s;

    attn_out[(size_t)row * T_ + fi] = p;

    const float* Vb = g_v + (size_t)bh * T_ * HD_;
    float a0 = 0.f, a1 = 0.f;
    #pragma unroll
    for (int j = 0; j < 32; j++) {
        float pp = __shfl_sync(FULL, p, j);
        int   ix = __shfl_sync(FULL, fi, j);
        const float* vr = Vb + (size_t)ix * HD_;
        a0 += pp * vr[lane];
        a1 += pp * vr[lane + 32];
    }
    int b = bh >> 3, h = bh & 7;
    float* o = g_ctx + ((size_t)(b * T_ + t)) * C_ + h * HD_;
    o[lane] = a0;
    o[lane + 32] = a1;
}

// ------------------- LayerNorm (two-pass, warp per row) -------------------
__global__ void __launch_bounds__(256) k_ln(const float* __restrict__ gamma,
                                            const float* __restrict__ beta)
{
    const unsigned FULL = 0xffffffffu;
    int warp = threadIdx.x >> 5, lane = threadIdx.x & 31;
    int row = blockIdx.x * 8 + warp;
    const float* x = g_analog + (size_t)row * C_;

    float v[16];
    float s = 0.f;
    #pragma unroll
    for (int i = 0; i < 16; i++) { v[i] = x[lane + 32 * i]; s += v[i]; }
    #pragma unroll
    for (int o = 16; o; o >>= 1) s += __shfl_xor_sync(FULL, s, o);
    float mu = s * (1.0f / 512.0f);

    float q = 0.f;
    #pragma unroll
    for (int i = 0; i < 16; i++) { float d = v[i] - mu; q += d * d; }
    #pragma unroll
    for (int o = 16; o; o >>= 1) q += __shfl_xor_sync(FULL, q, o);
    float var = q * (1.0f / 512.0f);
    float inv = 1.0f / sqrtf(var + 1e-5f);

    float* y = g_analog + (size_t)row * C_;
    #pragma unroll
    for (int i = 0; i < 16; i++) {
        int c = lane + 32 * i;
        y[c] = (v[i] - mu) * inv * gamma[c] + beta[c];
    }
}

// ------------------- adaptive LIF readout (one thread per (b,c) chain, 8-deep load batch) -------------------
__global__ void __launch_bounds__(256) k_lif(float* __restrict__ out)
{
    int idx = blockIdx.x * 256 + threadIdx.x;   // 0..2047 -> (b, c)
    int b = idx >> 9, c = idx & 511;
    const float* x = g_analog + (size_t)b * T_ * C_ + c;
    float* o = out + (size_t)b * T_ * C_ + c;

    float vm = 0.f, ad = 0.f;
    for (int t0 = 0; t0 < T_; t0 += 8) {
        float xt8[8];
        #pragma unroll
        for (int j = 0; j < 8; j++) xt8[j] = x[(size_t)(t0 + j) * C_];
        #pragma unroll
        for (int j = 0; j < 8; j++) {
            vm = 0.9f * vm + xt8[j];
            float th = 1.0f + 0.1f * ad;
            float u = vm - th;
            float sp = (u > 0.0f) ? 1.0f : 0.0f;
            vm = vm - sp * th;
            ad = 0.9f * ad + sp;
            o[(size_t)(t0 + j) * C_] = sp;
        }
    }
}

// ------------------- launch -------------------
extern "C" void kernel_launch(void* const* d_in, const int* in_sizes, int n_in,
                              void* d_out, int out_size)
{
    const float* x     = (const float*)d_in[0];
    const float* Wq    = (const float*)d_in[1];
    const float* bq    = (const float*)d_in[2];
    const float* Wk    = (const float*)d_in[3];
    const float* bk    = (const float*)d_in[4];
    const float* Wv    = (const float*)d_in[5];
    const float* bv    = (const float*)d_in[6];
    const float* Wo    = (const float*)d_in[7];
    const float* bo    = (const float*)d_in[8];
    const float* gamma = (const float*)d_in[9];
    const float* beta  = (const float*)d_in[10];

    float* out      = (float*)d_out;
    float* out_attn = out + SPIKES_SZ;

    const int smem_gemm = (2 * 128 * A_STRIDE + 2 * 32 * 128) * 4;   // 69632 B
    cudaFuncSetAttribute(k_gemm<0>, cudaFuncAttributeMaxDynamicSharedMemorySize, smem_gemm);
    cudaFuncSetAttribute(k_gemm<1>, cudaFuncAttributeMaxDynamicSharedMemorySize, smem_gemm);

    // 1) QKV projections (+ bf16 copies of q,k) -> g_q/g_k/g_v, g_qh/g_kh
    k_gemm<0><<<dim3(4, 64, 3), 256, smem_gemm>>>(x, Wq, Wk, Wv, bq, bk, bv);

    // 2) approx scores via bf16 mma.sync (tensor pipe) + attn zero-fill
    k_scores_mma<<<dim3(16, 16, 32), 256>>>(out_attn);

    // 3) approx top-64 + exact rescore + exact top-32 + softmax + scatter + context
    k_topkctx<<<ROWS_ / 8, 256>>>(out_attn);

    // 4) out projection -> g_analog
    k_gemm<1><<<dim3(4, 64, 1), 256, smem_gemm>>>(nullptr, Wo, Wo, Wo, bo, bo, bo);

    // 5) layernorm (in place)
    k_ln<<<(B_ * T_) / 8, 256>>>(gamma, beta);

    // 6) LIF readout -> spikes output
    k_lif<<<8, 256>>>(out);
}